// round 3
// baseline (speedup 1.0000x reference)
#include <cuda_runtime.h>
#include <cstdint>

// ---------------------------------------------------------------------------
// Problem constants
// ---------------------------------------------------------------------------
#define BATCH     2
#define NQ        4096
#define NK        4096
#define DIM       256
#define NHEADS    8
#define QK_DIM    128          // compressed q/k width
#define QK_HD     16           // per-head qk dim
#define V_HD      32           // per-head v dim
#define M_ROWS    (BATCH * NQ) // 8192
#define SCALE_F   0.17677669529663687f  // 32^-0.5

// ---------------------------------------------------------------------------
// Scratch (static device globals — allocation-free per harness rules)
// ---------------------------------------------------------------------------
__device__ float g_Q[M_ROWS * QK_DIM];   // 4 MB
__device__ float g_K[M_ROWS * QK_DIM];   // 4 MB
__device__ float g_V[M_ROWS * DIM];      // 8 MB
__device__ float g_O[M_ROWS * DIM];      // 8 MB

// ---------------------------------------------------------------------------
// Packed f32x2 helpers (Blackwell FFMA2)
// ---------------------------------------------------------------------------
__device__ __forceinline__ unsigned long long ffma2(unsigned long long a,
                                                    unsigned long long b,
                                                    unsigned long long c) {
    unsigned long long d;
    asm("fma.rn.f32x2 %0, %1, %2, %3;" : "=l"(d) : "l"(a), "l"(b), "l"(c));
    return d;
}
__device__ __forceinline__ float2 unpack2(unsigned long long v) {
    float2 f;
    asm("mov.b64 {%0, %1}, %2;" : "=f"(f.x), "=f"(f.y) : "l"(v));
    return f;
}
__device__ __forceinline__ unsigned long long pack2(float x, float y) {
    unsigned long long v;
    asm("mov.b64 %0, {%1, %2};" : "=l"(v) : "f"(x), "f"(y));
    return v;
}

// ---------------------------------------------------------------------------
// NT GEMM:  C[M,N] = A[M,K] * B[N,K]^T + bias[N]
// BM=BN=64, BK=32, 256 threads, 4x4 per-thread microtile.
// M,N,K all multiples of tile sizes for this problem (no bounds checks).
// ---------------------------------------------------------------------------
#define GBM 64
#define GBN 64
#define GBK 32
#define GPAD 4

__global__ __launch_bounds__(256) void gemm_nt_kernel(
    const float* __restrict__ A, const float* __restrict__ Bw,
    const float* __restrict__ bias, float* __restrict__ C,
    int M, int N, int K)
{
    __shared__ float As[GBK][GBM + GPAD];
    __shared__ float Bs[GBK][GBN + GPAD];

    const int tid = threadIdx.x;
    const int m0 = blockIdx.y * GBM;
    const int n0 = blockIdx.x * GBN;
    const int tx = tid & 15;       // 0..15 -> 4 cols each
    const int ty = tid >> 4;       // 0..15 -> 4 rows each

    float acc[4][4];
#pragma unroll
    for (int i = 0; i < 4; i++)
#pragma unroll
        for (int j = 0; j < 4; j++) acc[i][j] = 0.f;

    for (int k0 = 0; k0 < K; k0 += GBK) {
        // Load tiles (transposed into [k][m]/[k][n])
#pragma unroll
        for (int i = 0; i < 2; i++) {
            int e   = tid + i * 256;      // 0..511
            int row = e >> 3;             // 0..63
            int kq  = (e & 7) * 4;        // 0,4,...,28
            float4 a = *(const float4*)&A[(size_t)(m0 + row) * K + k0 + kq];
            As[kq + 0][row] = a.x; As[kq + 1][row] = a.y;
            As[kq + 2][row] = a.z; As[kq + 3][row] = a.w;
            float4 b = *(const float4*)&Bw[(size_t)(n0 + row) * K + k0 + kq];
            Bs[kq + 0][row] = b.x; Bs[kq + 1][row] = b.y;
            Bs[kq + 2][row] = b.z; Bs[kq + 3][row] = b.w;
        }
        __syncthreads();

#pragma unroll
        for (int k = 0; k < GBK; k++) {
            float4 a4 = *(const float4*)&As[k][ty * 4];
            float4 b4 = *(const float4*)&Bs[k][tx * 4];
            float av[4] = {a4.x, a4.y, a4.z, a4.w};
            float bv[4] = {b4.x, b4.y, b4.z, b4.w};
#pragma unroll
            for (int i = 0; i < 4; i++)
#pragma unroll
                for (int j = 0; j < 4; j++) acc[i][j] += av[i] * bv[j];
        }
        __syncthreads();
    }

    // Epilogue: bias + store (float4 per row)
    float4 bb = *(const float4*)&bias[n0 + tx * 4];
#pragma unroll
    for (int i = 0; i < 4; i++) {
        float4 o;
        o.x = acc[i][0] + bb.x;
        o.y = acc[i][1] + bb.y;
        o.z = acc[i][2] + bb.z;
        o.w = acc[i][3] + bb.w;
        *(float4*)&C[(size_t)(m0 + ty * 4 + i) * N + n0 + tx * 4] = o;
    }
}

// ---------------------------------------------------------------------------
// Fused flash attention (no online max: logits bounded ~|s|<8 so expf is safe)
// Grid: B * NQ/64 CTAs. Block: 512 threads = (head h = tid>>6, row r = tid&63).
// Warp == one head => K/V smem reads are pure broadcast.
// Bias tile stored transposed [k][r] => conflict-free per-thread reads.
// ---------------------------------------------------------------------------
#define AQ 64                  // q rows per CTA
#define AK 64                  // k cols per tile
#define ATHREADS 512
// smem floats: Ks 64*128, Vs 64*256, bs 64*65
#define KS_FLOATS (AK * QK_DIM)
#define VS_FLOATS (AK * DIM)
#define BS_STRIDE (AQ + 1)
#define BS_FLOATS (AK * BS_STRIDE)
#define ATT_SMEM_BYTES ((KS_FLOATS + VS_FLOATS + BS_FLOATS) * 4)

__global__ __launch_bounds__(ATHREADS, 1) void attn_kernel(
    const float* __restrict__ Q, const float* __restrict__ K,
    const float* __restrict__ V, const float* __restrict__ bias,
    float* __restrict__ O)
{
    extern __shared__ float smem[];
    float* Ks = smem;                       // [AK][128] linear
    float* Vs = Ks + KS_FLOATS;             // [AK][256] linear
    float* bs = Vs + VS_FLOATS;             // [AK][AQ+1] transposed bias

    const int tid = threadIdx.x;
    const int b   = blockIdx.x >> 6;        // NQ/64 = 64 blocks per batch
    const int q0  = (blockIdx.x & 63) * AQ;
    const int h   = tid >> 6;               // 0..7
    const int r   = tid & 63;               // 0..63

    const size_t qrow = (size_t)b * NQ + q0 + r;

    // Load this thread's q vector (16 floats) as 8 packed f32x2
    unsigned long long q2[8];
    {
        const ulonglong2* qp = (const ulonglong2*)(Q + qrow * QK_DIM + h * QK_HD);
#pragma unroll
        for (int i = 0; i < 4; i++) {
            ulonglong2 t = qp[i];
            q2[2 * i]     = t.x;
            q2[2 * i + 1] = t.y;
        }
    }

    unsigned long long acc2[16];
#pragma unroll
    for (int i = 0; i < 16; i++) acc2[i] = 0ULL;  // (0.f,0.f)
    float l = 0.f;

    const float* Kg0 = K + (size_t)b * NK * QK_DIM;
    const float* Vg0 = V + (size_t)b * NK * DIM;
    const float* Bg0 = bias + (size_t)b * NQ * NK;

    for (int kt = 0; kt < NK / AK; kt++) {
        __syncthreads();
        // --- cooperative tile loads ---
        {
            const float4* Kg = (const float4*)(Kg0 + (size_t)kt * AK * QK_DIM);
            float4* Ksd = (float4*)Ks;
#pragma unroll
            for (int i = 0; i < KS_FLOATS / 4 / ATHREADS; i++)
                Ksd[tid + i * ATHREADS] = Kg[tid + i * ATHREADS];

            const float4* Vg = (const float4*)(Vg0 + (size_t)kt * AK * DIM);
            float4* Vsd = (float4*)Vs;
#pragma unroll
            for (int i = 0; i < VS_FLOATS / 4 / ATHREADS; i++)
                Vsd[tid + i * ATHREADS] = Vg[tid + i * ATHREADS];

            // bias: [AQ rows][AK cols] -> transposed smem bs[k][r]
#pragma unroll
            for (int i = 0; i < 2; i++) {
                int c  = tid + i * ATHREADS;  // 0..1023
                int rl = c >> 4;              // 0..63
                int k4 = (c & 15) * 4;        // 0..60
                float4 bbv = *(const float4*)&Bg0[(size_t)(q0 + rl) * NK + kt * AK + k4];
                bs[(k4 + 0) * BS_STRIDE + rl] = bbv.x;
                bs[(k4 + 1) * BS_STRIDE + rl] = bbv.y;
                bs[(k4 + 2) * BS_STRIDE + rl] = bbv.z;
                bs[(k4 + 3) * BS_STRIDE + rl] = bbv.w;
            }
        }
        __syncthreads();

        // --- compute over AK keys ---
#pragma unroll 4
        for (int kk = 0; kk < AK; kk++) {
            // dot(q, K[kk]) over this head's 16 dims — broadcast smem reads
            const ulonglong2* kr = (const ulonglong2*)(Ks + kk * QK_DIM + h * QK_HD);
            unsigned long long s2 = 0ULL;
#pragma unroll
            for (int i = 0; i < 4; i++) {
                ulonglong2 t = kr[i];
                s2 = ffma2(q2[2 * i],     t.x, s2);
                s2 = ffma2(q2[2 * i + 1], t.y, s2);
            }
            float2 sp = unpack2(s2);
            float s = (sp.x + sp.y) * SCALE_F + bs[kk * BS_STRIDE + r];
            float p = __expf(s);
            l += p;
            unsigned long long p2 = pack2(p, p);

            const ulonglong2* vr = (const ulonglong2*)(Vs + kk * DIM + h * V_HD);
#pragma unroll
            for (int i = 0; i < 8; i++) {
                ulonglong2 v = vr[i];
                acc2[2 * i]     = ffma2(p2, v.x, acc2[2 * i]);
                acc2[2 * i + 1] = ffma2(p2, v.y, acc2[2 * i + 1]);
            }
        }
    }

    // --- epilogue: normalize and store O[b, q, h*32 + d] ---
    const float inv = 1.f / l;
    float* op = O + qrow * DIM + h * V_HD;
#pragma unroll
    for (int i = 0; i < 8; i++) {
        float2 e0 = unpack2(acc2[2 * i]);
        float2 e1 = unpack2(acc2[2 * i + 1]);
        float4 o;
        o.x = e0.x * inv; o.y = e0.y * inv;
        o.z = e1.x * inv; o.w = e1.y * inv;
        *(float4*)(op + i * 4) = o;
    }
}

// ---------------------------------------------------------------------------
// Launch
// Input order: query, key, value, att_bias, Wq, bq, Wk, bk, Wv, bv, Wo, bo
// ---------------------------------------------------------------------------
extern "C" void kernel_launch(void* const* d_in, const int* in_sizes, int n_in,
                              void* d_out, int out_size)
{
    (void)in_sizes; (void)n_in; (void)out_size;
    const float* query = (const float*)d_in[0];
    const float* key   = (const float*)d_in[1];
    const float* value = (const float*)d_in[2];
    const float* abias = (const float*)d_in[3];
    const float* Wq = (const float*)d_in[4];
    const float* bq = (const float*)d_in[5];
    const float* Wk = (const float*)d_in[6];
    const float* bk = (const float*)d_in[7];
    const float* Wv = (const float*)d_in[8];
    const float* bv = (const float*)d_in[9];
    const float* Wo = (const float*)d_in[10];
    const float* bo = (const float*)d_in[11];
    float* out = (float*)d_out;

    float *Qb, *Kb, *Vb, *Ob;
    cudaGetSymbolAddress((void**)&Qb, g_Q);
    cudaGetSymbolAddress((void**)&Kb, g_K);
    cudaGetSymbolAddress((void**)&Vb, g_V);
    cudaGetSymbolAddress((void**)&Ob, g_O);

    cudaFuncSetAttribute(attn_kernel,
                         cudaFuncAttributeMaxDynamicSharedMemorySize,
                         ATT_SMEM_BYTES);

    // Projections
    gemm_nt_kernel<<<dim3(QK_DIM / GBN, M_ROWS / GBM), 256>>>(
        query, Wq, bq, Qb, M_ROWS, QK_DIM, DIM);
    gemm_nt_kernel<<<dim3(QK_DIM / GBN, M_ROWS / GBM), 256>>>(
        key, Wk, bk, Kb, M_ROWS, QK_DIM, DIM);
    gemm_nt_kernel<<<dim3(DIM / GBN, M_ROWS / GBM), 256>>>(
        value, Wv, bv, Vb, M_ROWS, DIM, DIM);

    // Fused attention (all heads, bias shared)
    attn_kernel<<<BATCH * (NQ / AQ), ATHREADS, ATT_SMEM_BYTES>>>(
        Qb, Kb, Vb, abias, Ob);

    // Output projection
    gemm_nt_kernel<<<dim3(DIM / GBN, M_ROWS / GBM), 256>>>(
        Ob, Wo, bo, out, M_ROWS, DIM, DIM);
}

// round 5
// speedup vs baseline: 3.0906x; 3.0906x over previous
#include <cuda_runtime.h>
#include <cuda_fp16.h>
#include <cstdint>

#define BATCH     2
#define NQ        4096
#define NK        4096
#define DIM       256
#define QK_DIM    128
#define M_ROWS    (BATCH * NQ)
#define SCALE_F   0.17677669529663687f
#define LOG2E_F   1.4426950408889634f
#define QSCALE_F  (SCALE_F * LOG2E_F)
#define ACC_INIT  (-8.0f * LOG2E_F)

__device__ float  g_Q[M_ROWS * QK_DIM];   // scaled + tf32-rounded
__device__ float  g_K[M_ROWS * QK_DIM];   // tf32-rounded
__device__ __half g_Vh[M_ROWS * DIM];     // f16
__device__ float  g_O[M_ROWS * DIM];

// ---------------- PTX helpers ----------------
__device__ __forceinline__ uint32_t to_tf32(float f) {
    uint32_t r; asm("cvt.rna.tf32.f32 %0, %1;" : "=r"(r) : "f"(f)); return r;
}
__device__ __forceinline__ float ex2f(float y) {
    float e; asm("ex2.approx.ftz.f32 %0, %1;" : "=f"(e) : "f"(y)); return e;
}
__device__ __forceinline__ uint32_t f16x2_of(float hi, float lo) {
    uint32_t r; asm("cvt.rn.f16x2.f32 %0, %1, %2;" : "=r"(r) : "f"(hi), "f"(lo)); return r;
}
__device__ __forceinline__ void mma_tf32(float c[4], const uint32_t a[4],
                                         const uint32_t b[2]) {
    asm("mma.sync.aligned.m16n8k8.row.col.f32.tf32.tf32.f32 "
        "{%0,%1,%2,%3},{%4,%5,%6,%7},{%8,%9},{%0,%1,%2,%3};"
        : "+f"(c[0]), "+f"(c[1]), "+f"(c[2]), "+f"(c[3])
        : "r"(a[0]), "r"(a[1]), "r"(a[2]), "r"(a[3]), "r"(b[0]), "r"(b[1]));
}
__device__ __forceinline__ void mma_f16(float c[4], uint32_t a0, uint32_t a1,
                                        uint32_t a2, uint32_t a3,
                                        uint32_t b0, uint32_t b1) {
    asm("mma.sync.aligned.m16n8k16.row.col.f32.f16.f16.f32 "
        "{%0,%1,%2,%3},{%4,%5,%6,%7},{%8,%9},{%0,%1,%2,%3};"
        : "+f"(c[0]), "+f"(c[1]), "+f"(c[2]), "+f"(c[3])
        : "r"(a0), "r"(a1), "r"(a2), "r"(a3), "r"(b0), "r"(b1));
}
__device__ __forceinline__ void ldsm_x4_t(uint32_t& r0, uint32_t& r1,
                                          uint32_t& r2, uint32_t& r3, uint32_t a) {
    asm volatile("ldmatrix.sync.aligned.m8n8.x4.trans.shared.b16 {%0,%1,%2,%3},[%4];"
                 : "=r"(r0), "=r"(r1), "=r"(r2), "=r"(r3) : "r"(a));
}
__device__ __forceinline__ void cp_async16(uint32_t dst, const void* src) {
    asm volatile("cp.async.cg.shared.global [%0],[%1],16;" :: "r"(dst), "l"(src));
}

// ---------------- NT GEMM with typed epilogues ----------------
// MODE 0: f32   1: tf32-round   2: f16   3: (x*mulc) tf32-round
#define GBM 64
#define GBN 64
#define GBK 32

template <int MODE>
__global__ __launch_bounds__(256) void gemm_nt_kernel(
    const float* __restrict__ A, const float* __restrict__ Bw,
    const float* __restrict__ bias, void* __restrict__ Cv,
    int M, int N, int K, float mulc)
{
    __shared__ float As[GBK][GBM + 4];
    __shared__ float Bs[GBK][GBN + 4];
    const int tid = threadIdx.x;
    const int m0 = blockIdx.y * GBM, n0 = blockIdx.x * GBN;
    const int tx = tid & 15, ty = tid >> 4;

    float acc[4][4];
#pragma unroll
    for (int i = 0; i < 4; i++)
#pragma unroll
        for (int j = 0; j < 4; j++) acc[i][j] = 0.f;

    for (int k0 = 0; k0 < K; k0 += GBK) {
#pragma unroll
        for (int i = 0; i < 2; i++) {
            int e = tid + i * 256, row = e >> 3, kq = (e & 7) * 4;
            float4 a = *(const float4*)&A[(size_t)(m0 + row) * K + k0 + kq];
            As[kq + 0][row] = a.x; As[kq + 1][row] = a.y;
            As[kq + 2][row] = a.z; As[kq + 3][row] = a.w;
            float4 b = *(const float4*)&Bw[(size_t)(n0 + row) * K + k0 + kq];
            Bs[kq + 0][row] = b.x; Bs[kq + 1][row] = b.y;
            Bs[kq + 2][row] = b.z; Bs[kq + 3][row] = b.w;
        }
        __syncthreads();
#pragma unroll
        for (int k = 0; k < GBK; k++) {
            float4 a4 = *(const float4*)&As[k][ty * 4];
            float4 b4 = *(const float4*)&Bs[k][tx * 4];
            float av[4] = {a4.x, a4.y, a4.z, a4.w};
            float bv[4] = {b4.x, b4.y, b4.z, b4.w};
#pragma unroll
            for (int i = 0; i < 4; i++)
#pragma unroll
                for (int j = 0; j < 4; j++) acc[i][j] += av[i] * bv[j];
        }
        __syncthreads();
    }

    float4 bb = *(const float4*)&bias[n0 + tx * 4];
#pragma unroll
    for (int i = 0; i < 4; i++) {
        float v0 = acc[i][0] + bb.x, v1 = acc[i][1] + bb.y;
        float v2 = acc[i][2] + bb.z, v3 = acc[i][3] + bb.w;
        size_t off = (size_t)(m0 + ty * 4 + i) * N + n0 + tx * 4;
        if (MODE == 0) {
            float4 o = {v0, v1, v2, v3};
            *(float4*)((float*)Cv + off) = o;
        } else if (MODE == 1) {
            float4 o = {__uint_as_float(to_tf32(v0)), __uint_as_float(to_tf32(v1)),
                        __uint_as_float(to_tf32(v2)), __uint_as_float(to_tf32(v3))};
            *(float4*)((float*)Cv + off) = o;
        } else if (MODE == 2) {
            __half2* cp = (__half2*)((__half*)Cv + off);
            cp[0] = __floats2half2_rn(v0, v1);
            cp[1] = __floats2half2_rn(v2, v3);
        } else {
            float4 o = {__uint_as_float(to_tf32(v0 * mulc)),
                        __uint_as_float(to_tf32(v1 * mulc)),
                        __uint_as_float(to_tf32(v2 * mulc)),
                        __uint_as_float(to_tf32(v3 * mulc))};
            *(float4*)((float*)Cv + off) = o;
        }
    }
}

// ---------------- tensor-core fused flash attention ----------------
// CTA: 64 q-rows, all 8 heads. 16 warps: warp -> (head = w>>1, q-half = w&1).
// 128 tiles of 32 keys, 2-stage cp.async pipeline.
#define AK2        32
#define KT_ITERS   (NK / AK2)
#define ATHREADS   512
#define KS_STRIDE  528                         // bytes (132 floats)
#define VS_STRIDE  528                         // bytes (264 halves)
#define BSTR_B     144                         // bytes (36 floats)
#define OFF_V      (AK2 * KS_STRIDE)
#define OFF_B      (OFF_V + AK2 * VS_STRIDE)
#define STAGE_B    (OFF_B + 64 * BSTR_B)       // 43008
#define ATT_SMEM   (2 * STAGE_B)               // 86016

__global__ __launch_bounds__(ATHREADS, 1) void attn_mma_kernel(
    const float* __restrict__ Q, const float* __restrict__ K,
    const __half* __restrict__ Vh, const float* __restrict__ bias,
    float* __restrict__ O)
{
    extern __shared__ char smem[];
    const uint32_t s_u32 = (uint32_t)__cvta_generic_to_shared(smem);

    const int tid  = threadIdx.x;
    const int b    = blockIdx.x >> 6;
    const int q0   = (blockIdx.x & 63) * 64;
    const int warp = tid >> 5, lane = tid & 31;
    const int h    = warp >> 1, wq = warp & 1;
    const int g    = lane >> 2, i4 = lane & 3;

    const char* Kg = (const char*)(K  + (size_t)b * NK * QK_DIM);
    const char* Vg = (const char*)(Vh + (size_t)b * NK * DIM);
    const char* Bg = (const char*)(bias + (size_t)b * NQ * NK);

    // Q A-fragments (already scaled & tf32)
    uint32_t qa[2][2][4];
    {
        const float* Qb = Q + (size_t)(b * NQ + q0 + wq * 32) * QK_DIM;
#pragma unroll
        for (int m = 0; m < 2; m++)
#pragma unroll
            for (int s = 0; s < 2; s++) {
                int row = m * 16 + g, col = h * 16 + s * 8 + i4;
                qa[m][s][0] = __float_as_uint(Qb[(row)     * QK_DIM + col]);
                qa[m][s][1] = __float_as_uint(Qb[(row + 8) * QK_DIM + col]);
                qa[m][s][2] = __float_as_uint(Qb[(row)     * QK_DIM + col + 4]);
                qa[m][s][3] = __float_as_uint(Qb[(row + 8) * QK_DIM + col + 4]);
            }
    }

    float oacc[2][4][4];
#pragma unroll
    for (int m = 0; m < 2; m++)
#pragma unroll
        for (int d = 0; d < 4; d++)
#pragma unroll
            for (int e = 0; e < 4; e++) oacc[m][d][e] = 0.f;
    float lf[2][2] = {{0.f, 0.f}, {0.f, 0.f}};

    auto prefetch = [&](int kt, int st) {
        uint32_t sb = s_u32 + st * STAGE_B;
#pragma unroll
        for (int c = 0; c < 2; c++) {      // K tile: 32 x 512B
            int e = tid + c * ATHREADS, row = e >> 5, off = (e & 31) * 16;
            cp_async16(sb + row * KS_STRIDE + off,
                       Kg + (size_t)(kt * AK2 + row) * 512 + off);
        }
#pragma unroll
        for (int c = 0; c < 2; c++) {      // V tile (f16): 32 x 512B
            int e = tid + c * ATHREADS, row = e >> 5, off = (e & 31) * 16;
            cp_async16(sb + OFF_V + row * VS_STRIDE + off,
                       Vg + (size_t)(kt * AK2 + row) * 512 + off);
        }
        {                                  // bias tile: 64 x 128B
            int row = tid >> 3, off = (tid & 7) * 16;
            cp_async16(sb + OFF_B + row * BSTR_B + off,
                       Bg + (size_t)(q0 + row) * (NK * 4) + kt * (AK2 * 4) + off);
        }
    };

    prefetch(0, 0);
    asm volatile("cp.async.commit_group;");

    for (int kt = 0; kt < KT_ITERS; kt++) {
        const int st = kt & 1;
        if (kt + 1 < KT_ITERS) {
            prefetch(kt + 1, st ^ 1);
            asm volatile("cp.async.commit_group;");
            asm volatile("cp.async.wait_group 1;");
        } else {
            asm volatile("cp.async.wait_group 0;");
        }
        __syncthreads();

        const float* Ks = (const float*)(smem + st * STAGE_B);
        const float* Bs = (const float*)(smem + st * STAGE_B + OFF_B);
        const uint32_t vbase = s_u32 + st * STAGE_B + OFF_V;

        // S = Q*K^T (tf32), accumulators pre-offset by -8*log2e
        float sc[2][4][4];
#pragma unroll
        for (int m = 0; m < 2; m++)
#pragma unroll
            for (int nt = 0; nt < 4; nt++)
#pragma unroll
                for (int e = 0; e < 4; e++) sc[m][nt][e] = ACC_INIT;

#pragma unroll
        for (int nt = 0; nt < 4; nt++) {
            uint32_t kb[2][2];
#pragma unroll
            for (int s = 0; s < 2; s++) {
                const float* kr = Ks + (nt * 8 + g) * 132 + h * 16 + s * 8 + i4;
                kb[s][0] = __float_as_uint(kr[0]);
                kb[s][1] = __float_as_uint(kr[4]);
            }
#pragma unroll
            for (int m = 0; m < 2; m++) {
                mma_tf32(sc[m][nt], qa[m][0], kb[0]);
                mma_tf32(sc[m][nt], qa[m][1], kb[1]);
            }
        }

        // softmax: p = 2^(s + bias*log2e - 8*log2e), pack to f16 A-frags
        uint32_t pf[2][4][2];
#pragma unroll
        for (int m = 0; m < 2; m++) {
            const float* br0 = Bs + (wq * 32 + m * 16 + g) * 36;
            const float* br1 = br0 + 8 * 36;
#pragma unroll
            for (int nt = 0; nt < 4; nt++) {
                float2 blo = *(const float2*)(br0 + nt * 8 + 2 * i4);
                float2 bhi = *(const float2*)(br1 + nt * 8 + 2 * i4);
                float e0 = ex2f(fmaf(blo.x, LOG2E_F, sc[m][nt][0]));
                float e1 = ex2f(fmaf(blo.y, LOG2E_F, sc[m][nt][1]));
                float e2 = ex2f(fmaf(bhi.x, LOG2E_F, sc[m][nt][2]));
                float e3 = ex2f(fmaf(bhi.y, LOG2E_F, sc[m][nt][3]));
                lf[m][0] += e0 + e1;
                lf[m][1] += e2 + e3;
                pf[m][nt][0] = f16x2_of(e1, e0);
                pf[m][nt][1] = f16x2_of(e3, e2);
            }
        }

        // O += P*V  (f16 mma; V B-frags via ldmatrix.x4.trans)
        const int t8 = lane >> 3, r8 = lane & 7;
#pragma unroll
        for (int ks = 0; ks < 2; ks++) {
            uint32_t vb[4][2];
#pragma unroll
            for (int dp = 0; dp < 2; dp++) {
                int row  = ks * 16 + (t8 & 1) * 8 + r8;
                int colh = h * 32 + dp * 16 + (t8 >> 1) * 8;
                ldsm_x4_t(vb[dp * 2][0], vb[dp * 2][1],
                          vb[dp * 2 + 1][0], vb[dp * 2 + 1][1],
                          vbase + row * VS_STRIDE + colh * 2);
            }
#pragma unroll
            for (int m = 0; m < 2; m++) {
                uint32_t a0 = pf[m][2 * ks][0],     a1 = pf[m][2 * ks][1];
                uint32_t a2 = pf[m][2 * ks + 1][0], a3 = pf[m][2 * ks + 1][1];
#pragma unroll
                for (int dt = 0; dt < 4; dt++)
                    mma_f16(oacc[m][dt], a0, a1, a2, a3, vb[dt][0], vb[dt][1]);
            }
        }
        __syncthreads();
    }

    // reduce l over the 4 i-lanes, normalize, store
#pragma unroll
    for (int m = 0; m < 2; m++)
#pragma unroll
        for (int e = 0; e < 2; e++) {
            float v = lf[m][e];
            v += __shfl_xor_sync(0xFFFFFFFF, v, 1);
            v += __shfl_xor_sync(0xFFFFFFFF, v, 2);
            lf[m][e] = v;
        }
#pragma unroll
    for (int m = 0; m < 2; m++) {
        float inv0 = 1.f / lf[m][0], inv1 = 1.f / lf[m][1];
        int qlo = q0 + wq * 32 + m * 16 + g;
        float* o0 = O + ((size_t)b * NQ + qlo)     * DIM + h * 32 + 2 * i4;
        float* o1 = O + ((size_t)b * NQ + qlo + 8) * DIM + h * 32 + 2 * i4;
#pragma unroll
        for (int dt = 0; dt < 4; dt++) {
            float2 v0 = {oacc[m][dt][0] * inv0, oacc[m][dt][1] * inv0};
            float2 v1 = {oacc[m][dt][2] * inv1, oacc[m][dt][3] * inv1};
            *(float2*)(o0 + dt * 8) = v0;
            *(float2*)(o1 + dt * 8) = v1;
        }
    }
}

// ---------------- launch ----------------
extern "C" void kernel_launch(void* const* d_in, const int* in_sizes, int n_in,
                              void* d_out, int out_size)
{
    (void)in_sizes; (void)n_in; (void)out_size;
    const float* query = (const float*)d_in[0];
    const float* key   = (const float*)d_in[1];
    const float* value = (const float*)d_in[2];
    const float* abias = (const float*)d_in[3];
    const float* Wq = (const float*)d_in[4];
    const float* bq = (const float*)d_in[5];
    const float* Wk = (const float*)d_in[6];
    const float* bk = (const float*)d_in[7];
    const float* Wv = (const float*)d_in[8];
    const float* bv = (const float*)d_in[9];
    const float* Wo = (const float*)d_in[10];
    const float* bo = (const float*)d_in[11];
    float* out = (float*)d_out;

    float *Qb, *Kb, *Ob;
    __half* Vb;
    cudaGetSymbolAddress((void**)&Qb, g_Q);
    cudaGetSymbolAddress((void**)&Kb, g_K);
    cudaGetSymbolAddress((void**)&Vb, g_Vh);
    cudaGetSymbolAddress((void**)&Ob, g_O);

    cudaFuncSetAttribute(attn_mma_kernel,
                         cudaFuncAttributeMaxDynamicSharedMemorySize, ATT_SMEM);

    // Projections: Q scaled+tf32, K tf32, V f16
    gemm_nt_kernel<3><<<dim3(QK_DIM / GBN, M_ROWS / GBM), 256>>>(
        query, Wq, bq, Qb, M_ROWS, QK_DIM, DIM, QSCALE_F);
    gemm_nt_kernel<1><<<dim3(QK_DIM / GBN, M_ROWS / GBM), 256>>>(
        key, Wk, bk, Kb, M_ROWS, QK_DIM, DIM, 0.f);
    gemm_nt_kernel<2><<<dim3(DIM / GBN, M_ROWS / GBM), 256>>>(
        value, Wv, bv, Vb, M_ROWS, DIM, DIM, 0.f);

    attn_mma_kernel<<<BATCH * (NQ / 64), ATHREADS, ATT_SMEM>>>(
        Qb, Kb, Vb, abias, Ob);

    gemm_nt_kernel<0><<<dim3(DIM / GBN, M_ROWS / GBM), 256>>>(
        Ob, Wo, bo, out, M_ROWS, DIM, DIM, 0.f);
}

// round 7
// speedup vs baseline: 3.4013x; 1.1005x over previous
#include <cuda_runtime.h>
#include <cuda_fp16.h>
#include <cstdint>

#define BATCH     2
#define NQ        4096
#define NK        4096
#define DIM       256
#define QK_DIM    128
#define M_ROWS    (BATCH * NQ)
#define SCALE_F   0.17677669529663687f
#define LOG2E_F   1.4426950408889634f
#define QSCALE_F  (SCALE_F * LOG2E_F)
#define ACC_INIT  (-8.0f * LOG2E_F)

__device__ __half g_Qh[M_ROWS * QK_DIM];  // scaled by SCALE*log2e, f16
__device__ __half g_Kh[M_ROWS * QK_DIM];  // f16
__device__ __half g_Vh[M_ROWS * DIM];     // f16
__device__ float  g_O[M_ROWS * DIM];

// ---------------- PTX helpers ----------------
__device__ __forceinline__ float ex2f(float y) {
    float e; asm("ex2.approx.ftz.f32 %0, %1;" : "=f"(e) : "f"(y)); return e;
}
__device__ __forceinline__ uint32_t f16x2_of(float hi, float lo) {
    uint32_t r; asm("cvt.rn.f16x2.f32 %0, %1, %2;" : "=r"(r) : "f"(hi), "f"(lo)); return r;
}
__device__ __forceinline__ void mma_f16(float c[4], uint32_t a0, uint32_t a1,
                                        uint32_t a2, uint32_t a3,
                                        uint32_t b0, uint32_t b1) {
    asm("mma.sync.aligned.m16n8k16.row.col.f32.f16.f16.f32 "
        "{%0,%1,%2,%3},{%4,%5,%6,%7},{%8,%9},{%0,%1,%2,%3};"
        : "+f"(c[0]), "+f"(c[1]), "+f"(c[2]), "+f"(c[3])
        : "r"(a0), "r"(a1), "r"(a2), "r"(a3), "r"(b0), "r"(b1));
}
__device__ __forceinline__ void ldsm_x4(uint32_t& r0, uint32_t& r1,
                                        uint32_t& r2, uint32_t& r3, uint32_t a) {
    asm volatile("ldmatrix.sync.aligned.m8n8.x4.shared.b16 {%0,%1,%2,%3},[%4];"
                 : "=r"(r0), "=r"(r1), "=r"(r2), "=r"(r3) : "r"(a));
}
__device__ __forceinline__ void ldsm_x4_t(uint32_t& r0, uint32_t& r1,
                                          uint32_t& r2, uint32_t& r3, uint32_t a) {
    asm volatile("ldmatrix.sync.aligned.m8n8.x4.trans.shared.b16 {%0,%1,%2,%3},[%4];"
                 : "=r"(r0), "=r"(r1), "=r"(r2), "=r"(r3) : "r"(a));
}
__device__ __forceinline__ void cp_async16(uint32_t dst, const void* src) {
    asm volatile("cp.async.cg.shared.global [%0],[%1],16;" :: "r"(dst), "l"(src));
}

// ---------------- NT GEMM with typed epilogues ----------------
// MODE 0: f32   2: f16   4: f16 of (x*mulc)
#define GBM 64
#define GBN 64
#define GBK 32

template <int MODE>
__global__ __launch_bounds__(256) void gemm_nt_kernel(
    const float* __restrict__ A, const float* __restrict__ Bw,
    const float* __restrict__ bias, void* __restrict__ Cv,
    int M, int N, int K, float mulc)
{
    __shared__ float As[GBK][GBM + 4];
    __shared__ float Bs[GBK][GBN + 4];
    const int tid = threadIdx.x;
    const int m0 = blockIdx.y * GBM, n0 = blockIdx.x * GBN;
    const int tx = tid & 15, ty = tid >> 4;

    float acc[4][4];
#pragma unroll
    for (int i = 0; i < 4; i++)
#pragma unroll
        for (int j = 0; j < 4; j++) acc[i][j] = 0.f;

    for (int k0 = 0; k0 < K; k0 += GBK) {
#pragma unroll
        for (int i = 0; i < 2; i++) {
            int e = tid + i * 256, row = e >> 3, kq = (e & 7) * 4;
            float4 a = *(const float4*)&A[(size_t)(m0 + row) * K + k0 + kq];
            As[kq + 0][row] = a.x; As[kq + 1][row] = a.y;
            As[kq + 2][row] = a.z; As[kq + 3][row] = a.w;
            float4 b = *(const float4*)&Bw[(size_t)(n0 + row) * K + k0 + kq];
            Bs[kq + 0][row] = b.x; Bs[kq + 1][row] = b.y;
            Bs[kq + 2][row] = b.z; Bs[kq + 3][row] = b.w;
        }
        __syncthreads();
#pragma unroll
        for (int k = 0; k < GBK; k++) {
            float4 a4 = *(const float4*)&As[k][ty * 4];
            float4 b4 = *(const float4*)&Bs[k][tx * 4];
            float av[4] = {a4.x, a4.y, a4.z, a4.w};
            float bv[4] = {b4.x, b4.y, b4.z, b4.w};
#pragma unroll
            for (int i = 0; i < 4; i++)
#pragma unroll
                for (int j = 0; j < 4; j++) acc[i][j] += av[i] * bv[j];
        }
        __syncthreads();
    }

    float4 bb = *(const float4*)&bias[n0 + tx * 4];
#pragma unroll
    for (int i = 0; i < 4; i++) {
        float v0 = acc[i][0] + bb.x, v1 = acc[i][1] + bb.y;
        float v2 = acc[i][2] + bb.z, v3 = acc[i][3] + bb.w;
        size_t off = (size_t)(m0 + ty * 4 + i) * N + n0 + tx * 4;
        if (MODE == 0) {
            float4 o = {v0, v1, v2, v3};
            *(float4*)((float*)Cv + off) = o;
        } else if (MODE == 2) {
            __half2* cp = (__half2*)((__half*)Cv + off);
            cp[0] = __floats2half2_rn(v0, v1);
            cp[1] = __floats2half2_rn(v2, v3);
        } else {
            __half2* cp = (__half2*)((__half*)Cv + off);
            cp[0] = __floats2half2_rn(v0 * mulc, v1 * mulc);
            cp[1] = __floats2half2_rn(v2 * mulc, v3 * mulc);
        }
    }
}

// ---------------- tensor-core fused flash attention ----------------
// CTA: 32 q-rows x 8 heads, 256 threads (warp = head), 2 CTAs/SM.
// 128 tiles of 32 keys, 2-stage cp.async pipeline, all-f16 mma.
#define AK2        32
#define KT_ITERS   (NK / AK2)
#define ATHREADS   256
#define KS_STRIDE  272                    // bytes (128 f16 data + 16B pad)
#define VS_STRIDE  528                    // bytes (256 f16 data + 16B pad)
#define BSTR_B     144                    // bytes (32 f32 data + pad)
#define OFF_V      (AK2 * KS_STRIDE)      // 8704
#define OFF_B      (OFF_V + AK2 * VS_STRIDE)  // 25600
#define STAGE_B    (OFF_B + 32 * BSTR_B)  // 30208
#define ATT_SMEM   (2 * STAGE_B)          // 60416

__global__ __launch_bounds__(ATHREADS, 2) void attn_mma_kernel(
    const __half* __restrict__ Q, const __half* __restrict__ K,
    const __half* __restrict__ Vh, const float* __restrict__ bias,
    float* __restrict__ O)
{
    extern __shared__ char smem[];
    const uint32_t s_u32 = (uint32_t)__cvta_generic_to_shared(smem);

    const int tid  = threadIdx.x;
    const int b    = blockIdx.x >> 7;           // 128 q-blocks per batch
    const int q0   = (blockIdx.x & 127) * 32;
    const int h    = tid >> 5;                  // warp = head
    const int lane = tid & 31;
    const int g    = lane >> 2, i4 = lane & 3;

    const char* Kg = (const char*)(K  + (size_t)b * NK * QK_DIM);
    const char* Vg = (const char*)(Vh + (size_t)b * NK * DIM);
    const char* Bg = (const char*)(bias + (size_t)b * NQ * NK);

    // Q A-fragments, f16 (already scaled by SCALE*log2e)
    uint32_t qa[2][4];
    {
        const uint32_t* Qb = (const uint32_t*)(Q + (size_t)(b * NQ + q0) * QK_DIM);
#pragma unroll
        for (int m = 0; m < 2; m++) {
            int r0 = m * 16 + g;
            qa[m][0] = Qb[(r0)     * 64 + h * 8 + i4];
            qa[m][1] = Qb[(r0 + 8) * 64 + h * 8 + i4];
            qa[m][2] = Qb[(r0)     * 64 + h * 8 + 4 + i4];
            qa[m][3] = Qb[(r0 + 8) * 64 + h * 8 + 4 + i4];
        }
    }

    float oacc[2][4][4];
#pragma unroll
    for (int m = 0; m < 2; m++)
#pragma unroll
        for (int d = 0; d < 4; d++)
#pragma unroll
            for (int e = 0; e < 4; e++) oacc[m][d][e] = 0.f;
    float lf[2][2] = {{0.f, 0.f}, {0.f, 0.f}};

    auto prefetch = [&](int kt, int st) {
        uint32_t sb = s_u32 + st * STAGE_B;
#pragma unroll
        for (int c = 0; c < 2; c++) {      // K tile f16: 32 x 256B
            int e = tid + c * ATHREADS, row = e >> 4, off = (e & 15) * 16;
            cp_async16(sb + row * KS_STRIDE + off,
                       Kg + (size_t)(kt * AK2 + row) * 256 + off);
        }
#pragma unroll
        for (int c = 0; c < 4; c++) {      // V tile f16: 32 x 512B
            int e = tid + c * ATHREADS, row = e >> 5, off = (e & 31) * 16;
            cp_async16(sb + OFF_V + row * VS_STRIDE + off,
                       Vg + (size_t)(kt * AK2 + row) * 512 + off);
        }
        {                                  // bias tile f32: 32 x 128B
            int row = tid >> 3, off = (tid & 7) * 16;
            cp_async16(sb + OFF_B + row * BSTR_B + off,
                       Bg + (size_t)(q0 + row) * (NK * 4) + kt * (AK2 * 4) + off);
        }
    };

    prefetch(0, 0);
    asm volatile("cp.async.commit_group;");

    for (int kt = 0; kt < KT_ITERS; kt++) {
        const int st = kt & 1;
        if (kt + 1 < KT_ITERS) {
            prefetch(kt + 1, st ^ 1);
            asm volatile("cp.async.commit_group;");
            asm volatile("cp.async.wait_group 1;");
        } else {
            asm volatile("cp.async.wait_group 0;");
        }
        __syncthreads();

        const uint32_t kbase = s_u32 + st * STAGE_B;
        const uint32_t vbase = kbase + OFF_V;
        const float*   Bs    = (const float*)(smem + st * STAGE_B + OFF_B);

        // K B-fragments: 2x ldmatrix.x4 (16 keys each, head slice 16 f16)
        uint32_t kb[4][2];
        {
            const int mat = lane >> 3, r8 = lane & 7;
#pragma unroll
            for (int ntp = 0; ntp < 2; ntp++) {
                int row = ntp * 16 + r8 + (mat >> 1) * 8;
                uint32_t addr = kbase + row * KS_STRIDE + h * 32 + (mat & 1) * 16;
                ldsm_x4(kb[ntp * 2][0], kb[ntp * 2][1],
                        kb[ntp * 2 + 1][0], kb[ntp * 2 + 1][1], addr);
            }
        }

        // S = Q*K^T (f16), accumulators pre-offset by -8*log2e
        float sc[2][4][4];
#pragma unroll
        for (int m = 0; m < 2; m++)
#pragma unroll
            for (int nt = 0; nt < 4; nt++) {
#pragma unroll
                for (int e = 0; e < 4; e++) sc[m][nt][e] = ACC_INIT;
                mma_f16(sc[m][nt], qa[m][0], qa[m][1], qa[m][2], qa[m][3],
                        kb[nt][0], kb[nt][1]);
            }

        // softmax: p = 2^(s + bias*log2e - 8*log2e), pack to f16 A-frags
        uint32_t pf[2][4][2];
#pragma unroll
        for (int m = 0; m < 2; m++) {
            const float* br0 = Bs + (m * 16 + g) * 36;
            const float* br1 = br0 + 8 * 36;
#pragma unroll
            for (int nt = 0; nt < 4; nt++) {
                float2 blo = *(const float2*)(br0 + nt * 8 + 2 * i4);
                float2 bhi = *(const float2*)(br1 + nt * 8 + 2 * i4);
                float e0 = ex2f(fmaf(blo.x, LOG2E_F, sc[m][nt][0]));
                float e1 = ex2f(fmaf(blo.y, LOG2E_F, sc[m][nt][1]));
                float e2 = ex2f(fmaf(bhi.x, LOG2E_F, sc[m][nt][2]));
                float e3 = ex2f(fmaf(bhi.y, LOG2E_F, sc[m][nt][3]));
                lf[m][0] += e0 + e1;
                lf[m][1] += e2 + e3;
                pf[m][nt][0] = f16x2_of(e1, e0);
                pf[m][nt][1] = f16x2_of(e3, e2);
            }
        }

        // O += P*V  (f16 mma; V B-frags via ldmatrix.x4.trans)
        const int t8 = lane >> 3, r8 = lane & 7;
#pragma unroll
        for (int ks = 0; ks < 2; ks++) {
            uint32_t vb[4][2];
#pragma unroll
            for (int dp = 0; dp < 2; dp++) {
                int row  = ks * 16 + (t8 & 1) * 8 + r8;
                int colh = h * 32 + dp * 16 + (t8 >> 1) * 8;
                ldsm_x4_t(vb[dp * 2][0], vb[dp * 2][1],
                          vb[dp * 2 + 1][0], vb[dp * 2 + 1][1],
                          vbase + row * VS_STRIDE + colh * 2);
            }
#pragma unroll
            for (int m = 0; m < 2; m++) {
                uint32_t a0 = pf[m][2 * ks][0],     a1 = pf[m][2 * ks][1];
                uint32_t a2 = pf[m][2 * ks + 1][0], a3 = pf[m][2 * ks + 1][1];
#pragma unroll
                for (int dt = 0; dt < 4; dt++)
                    mma_f16(oacc[m][dt], a0, a1, a2, a3, vb[dt][0], vb[dt][1]);
            }
        }
        __syncthreads();
    }

    // reduce l over the 4 i-lanes, normalize, store
#pragma unroll
    for (int m = 0; m < 2; m++)
#pragma unroll
        for (int e = 0; e < 2; e++) {
            float v = lf[m][e];
            v += __shfl_xor_sync(0xFFFFFFFF, v, 1);
            v += __shfl_xor_sync(0xFFFFFFFF, v, 2);
            lf[m][e] = v;
        }
#pragma unroll
    for (int m = 0; m < 2; m++) {
        float inv0 = 1.f / lf[m][0], inv1 = 1.f / lf[m][1];
        int qlo = q0 + m * 16 + g;
        float* o0 = O + ((size_t)b * NQ + qlo)     * DIM + h * 32 + 2 * i4;
        float* o1 = O + ((size_t)b * NQ + qlo + 8) * DIM + h * 32 + 2 * i4;
#pragma unroll
        for (int dt = 0; dt < 4; dt++) {
            float2 v0 = {oacc[m][dt][0] * inv0, oacc[m][dt][1] * inv0};
            float2 v1 = {oacc[m][dt][2] * inv1, oacc[m][dt][3] * inv1};
            *(float2*)(o0 + dt * 8) = v0;
            *(float2*)(o1 + dt * 8) = v1;
        }
    }
}

// ---------------- launch ----------------
extern "C" void kernel_launch(void* const* d_in, const int* in_sizes, int n_in,
                              void* d_out, int out_size)
{
    (void)in_sizes; (void)n_in; (void)out_size;
    const float* query = (const float*)d_in[0];
    const float* key   = (const float*)d_in[1];
    const float* value = (const float*)d_in[2];
    const float* abias = (const float*)d_in[3];
    const float* Wq = (const float*)d_in[4];
    const float* bq = (const float*)d_in[5];
    const float* Wk = (const float*)d_in[6];
    const float* bk = (const float*)d_in[7];
    const float* Wv = (const float*)d_in[8];
    const float* bv = (const float*)d_in[9];
    const float* Wo = (const float*)d_in[10];
    const float* bo = (const float*)d_in[11];
    float* out = (float*)d_out;

    __half *Qb, *Kb, *Vb;
    float* Ob;
    cudaGetSymbolAddress((void**)&Qb, g_Qh);
    cudaGetSymbolAddress((void**)&Kb, g_Kh);
    cudaGetSymbolAddress((void**)&Vb, g_Vh);
    cudaGetSymbolAddress((void**)&Ob, g_O);

    cudaFuncSetAttribute(attn_mma_kernel,
                         cudaFuncAttributeMaxDynamicSharedMemorySize, ATT_SMEM);

    // Projections: Q f16 scaled, K f16, V f16
    gemm_nt_kernel<4><<<dim3(QK_DIM / GBN, M_ROWS / GBM), 256>>>(
        query, Wq, bq, Qb, M_ROWS, QK_DIM, DIM, QSCALE_F);
    gemm_nt_kernel<2><<<dim3(QK_DIM / GBN, M_ROWS / GBM), 256>>>(
        key, Wk, bk, Kb, M_ROWS, QK_DIM, DIM, 0.f);
    gemm_nt_kernel<2><<<dim3(DIM / GBN, M_ROWS / GBM), 256>>>(
        value, Wv, bv, Vb, M_ROWS, DIM, DIM, 0.f);

    attn_mma_kernel<<<BATCH * (NQ / 32), ATHREADS, ATT_SMEM>>>(
        Qb, Kb, Vb, abias, Ob);

    gemm_nt_kernel<0><<<dim3(DIM / GBN, M_ROWS / GBM), 256>>>(
        Ob, Wo, bo, out, M_ROWS, DIM, DIM, 0.f);
}